// round 5
// baseline (speedup 1.0000x reference)
#include <cuda_runtime.h>
#include <math.h>

// s = sum_i R[i] * ||Z[i,:]||^2 ; out = 1 - exp(-exp(s))
// Z: [N,128] fp32 row-major, R: [N] fp32. Pure HBM-bound reduction.

#define NBLOCKS 2048
#define NTHREADS 256

// Scratch for deterministic two-pass reduction (no cudaMalloc allowed).
static __device__ float g_partials[NBLOCKS];

__global__ __launch_bounds__(NTHREADS) void bp_reduce_kernel(
    const float* __restrict__ Z, const float* __restrict__ R, int nrows)
{
    const float4* __restrict__ Z4 = reinterpret_cast<const float4*>(Z);
    const int total4 = nrows * 32;               // 128 floats = 32 float4 per row
    const int stride = gridDim.x * blockDim.x;

    float acc = 0.0f;
    for (int j = blockIdx.x * blockDim.x + threadIdx.x; j < total4; j += stride) {
        float4 v = Z4[j];
        int row = j >> 5;                        // j / 32
        float d = v.x * v.x + v.y * v.y + v.z * v.z + v.w * v.w;
        acc = fmaf(d, __ldg(&R[row]), acc);
    }

    // warp reduce
    #pragma unroll
    for (int o = 16; o > 0; o >>= 1)
        acc += __shfl_xor_sync(0xffffffffu, acc, o);

    __shared__ float smem[NTHREADS / 32];
    if ((threadIdx.x & 31) == 0) smem[threadIdx.x >> 5] = acc;
    __syncthreads();

    if (threadIdx.x < NTHREADS / 32) {
        float v = smem[threadIdx.x];
        #pragma unroll
        for (int o = (NTHREADS / 32) / 2; o > 0; o >>= 1)
            v += __shfl_xor_sync(0xffffffffu, v, o);
        if (threadIdx.x == 0) g_partials[blockIdx.x] = v;
    }
}

__global__ __launch_bounds__(1024) void bp_finalize_kernel(float* __restrict__ out)
{
    double acc = 0.0;
    for (int i = threadIdx.x; i < NBLOCKS; i += 1024)
        acc += (double)g_partials[i];

    #pragma unroll
    for (int o = 16; o > 0; o >>= 1)
        acc += __shfl_xor_sync(0xffffffffu, acc, o);

    __shared__ double smem[32];
    if ((threadIdx.x & 31) == 0) smem[threadIdx.x >> 5] = acc;
    __syncthreads();

    if (threadIdx.x < 32) {
        double v = smem[threadIdx.x];
        #pragma unroll
        for (int o = 16; o > 0; o >>= 1)
            v += __shfl_xor_sync(0xffffffffu, v, o);
        if (threadIdx.x == 0) {
            double s = v;
            double lam = exp(s);
            out[0] = (float)(1.0 - exp(-lam));
        }
    }
}

extern "C" void kernel_launch(void* const* d_in, const int* in_sizes, int n_in,
                              void* d_out, int out_size)
{
    const float* a0 = (const float*)d_in[0];
    const float* a1 = (const float*)d_in[1];
    // Z is the big [N,128] tensor, R is the [N] vector; pick by size.
    const float* Z;
    const float* R;
    int nrows;
    if (in_sizes[0] >= in_sizes[1]) { Z = a0; R = a1; nrows = in_sizes[1]; }
    else                            { Z = a1; R = a0; nrows = in_sizes[0]; }

    bp_reduce_kernel<<<NBLOCKS, NTHREADS>>>(Z, R, nrows);
    bp_finalize_kernel<<<1, 1024>>>((float*)d_out);
}

// round 7
// speedup vs baseline: 1.0412x; 1.0412x over previous
#include <cuda_runtime.h>
#include <math.h>

// s = sum_i R[i] * ||Z[i,:]||^2 ; out = 1 - exp(-exp(s))
// Z: [N,128] fp32 row-major (256 MB), R: [N] fp32 (2 MB). HBM-bound reduction.
// Single fused kernel: last arriving block performs the final deterministic sum.

#define NBLOCKS  2048
#define NTHREADS 256

static __device__ float        g_partials[NBLOCKS];
static __device__ unsigned int g_arrive = 0;   // wraps back to 0 each launch

__global__ __launch_bounds__(NTHREADS) void bp_fused_kernel(
    const float* __restrict__ Z, const float* __restrict__ R, int nrows,
    float* __restrict__ out)
{
    const float4* __restrict__ Z4 = reinterpret_cast<const float4*>(Z);
    const int total4 = nrows * 32;                    // 32 float4 per 128-wide row
    const int stride = gridDim.x * blockDim.x;        // threads in grid
    const int tid    = blockIdx.x * blockDim.x + threadIdx.x;

    float a0 = 0.f, a1 = 0.f, a2 = 0.f, a3 = 0.f;

    int j = tid;
    // Unroll x4 with independent accumulators -> 4 batched LDG.128 + 4 R loads
    // in flight per trip (MLP >= 8), to saturate HBM.
    for (; j + 3 * stride < total4; j += 4 * stride) {
        float4 v0 = Z4[j];
        float4 v1 = Z4[j +     stride];
        float4 v2 = Z4[j + 2 * stride];
        float4 v3 = Z4[j + 3 * stride];
        float  r0 = __ldg(&R[(j             ) >> 5]);
        float  r1 = __ldg(&R[(j +     stride) >> 5]);
        float  r2 = __ldg(&R[(j + 2 * stride) >> 5]);
        float  r3 = __ldg(&R[(j + 3 * stride) >> 5]);
        a0 = fmaf(v0.x*v0.x + v0.y*v0.y + v0.z*v0.z + v0.w*v0.w, r0, a0);
        a1 = fmaf(v1.x*v1.x + v1.y*v1.y + v1.z*v1.z + v1.w*v1.w, r1, a1);
        a2 = fmaf(v2.x*v2.x + v2.y*v2.y + v2.z*v2.z + v2.w*v2.w, r2, a2);
        a3 = fmaf(v3.x*v3.x + v3.y*v3.y + v3.z*v3.z + v3.w*v3.w, r3, a3);
    }
    for (; j < total4; j += stride) {
        float4 v = Z4[j];
        float  r = __ldg(&R[j >> 5]);
        a0 = fmaf(v.x*v.x + v.y*v.y + v.z*v.z + v.w*v.w, r, a0);
    }

    float acc = (a0 + a1) + (a2 + a3);

    // warp reduce
    #pragma unroll
    for (int o = 16; o > 0; o >>= 1)
        acc += __shfl_xor_sync(0xffffffffu, acc, o);

    __shared__ float smem[NTHREADS / 32];
    if ((threadIdx.x & 31) == 0) smem[threadIdx.x >> 5] = acc;
    __syncthreads();

    if (threadIdx.x < 32) {
        float v = (threadIdx.x < NTHREADS / 32) ? smem[threadIdx.x] : 0.f;
        #pragma unroll
        for (int o = (NTHREADS / 32) / 2; o > 0; o >>= 1)
            v += __shfl_xor_sync(0xffffffffu, v, o);
        if (threadIdx.x == 0) g_partials[blockIdx.x] = v;
    }

    // ---- last block finalizes (deterministic: fixed-order sum of partials) ----
    __shared__ bool is_last;
    __threadfence();                                  // partials visible grid-wide
    if (threadIdx.x == 0) {
        unsigned int prev = atomicInc(&g_arrive, NBLOCKS - 1); // wraps -> auto-reset
        is_last = (prev == NBLOCKS - 1);
    }
    __syncthreads();
    if (!is_last) return;

    double dacc = 0.0;
    for (int i = threadIdx.x; i < NBLOCKS; i += NTHREADS)
        dacc += (double)g_partials[i];

    #pragma unroll
    for (int o = 16; o > 0; o >>= 1)
        dacc += __shfl_xor_sync(0xffffffffu, dacc, o);

    __shared__ double dsmem[NTHREADS / 32];
    if ((threadIdx.x & 31) == 0) dsmem[threadIdx.x >> 5] = dacc;
    __syncthreads();

    if (threadIdx.x == 0) {
        double s = 0.0;
        #pragma unroll
        for (int w = 0; w < NTHREADS / 32; w++) s += dsmem[w];
        double lam = exp(s);
        out[0] = (float)(1.0 - exp(-lam));
    }
}

extern "C" void kernel_launch(void* const* d_in, const int* in_sizes, int n_in,
                              void* d_out, int out_size)
{
    const float* a0 = (const float*)d_in[0];
    const float* a1 = (const float*)d_in[1];
    const float* Z; const float* R; int nrows;
    if (in_sizes[0] >= in_sizes[1]) { Z = a0; R = a1; nrows = in_sizes[1]; }
    else                            { Z = a1; R = a0; nrows = in_sizes[0]; }

    bp_fused_kernel<<<NBLOCKS, NTHREADS>>>(Z, R, nrows, (float*)d_out);
}

// round 8
// speedup vs baseline: 1.1340x; 1.0891x over previous
#include <cuda_runtime.h>
#include <math.h>

// s = sum_i R[i] * ||Z[i,:]||^2 ; out = 1 - exp(-exp(s))
// Z: [N,128] fp32 row-major (256 MB), R: [N] fp32 (2 MB). HBM-bound reduction.
// Single fused kernel, single resident wave (1184 CTAs = 148x8; fits 8 CTAs/SM
// at 32 regs so the whole grid is co-resident -> no wave quantization).

#define NBLOCKS  1184
#define NTHREADS 256

static __device__ float        g_partials[NBLOCKS];
static __device__ unsigned int g_arrive = 0;   // wraps back to 0 each launch

__global__ __launch_bounds__(NTHREADS, 8) void bp_fused_kernel(
    const float* __restrict__ Z, const float* __restrict__ R, int nrows,
    float* __restrict__ out)
{
    const float4* __restrict__ Z4 = reinterpret_cast<const float4*>(Z);
    const int total4 = nrows * 32;                    // 32 float4 per 128-wide row
    const int stride = gridDim.x * blockDim.x;        // threads in grid
    const int tid    = blockIdx.x * blockDim.x + threadIdx.x;

    float a0 = 0.f, a1 = 0.f, a2 = 0.f, a3 = 0.f;

    int j = tid;
    // Unroll x4, independent accumulators -> 4 front-batched LDG.128 + 4 R loads
    // in flight per trip. Regs stay <=32 so 8 CTAs/SM remain resident.
    for (; j + 3 * stride < total4; j += 4 * stride) {
        float4 v0 = Z4[j];
        float4 v1 = Z4[j +     stride];
        float4 v2 = Z4[j + 2 * stride];
        float4 v3 = Z4[j + 3 * stride];
        float  r0 = __ldg(&R[(j             ) >> 5]);
        float  r1 = __ldg(&R[(j +     stride) >> 5]);
        float  r2 = __ldg(&R[(j + 2 * stride) >> 5]);
        float  r3 = __ldg(&R[(j + 3 * stride) >> 5]);
        a0 = fmaf(v0.x*v0.x + v0.y*v0.y + v0.z*v0.z + v0.w*v0.w, r0, a0);
        a1 = fmaf(v1.x*v1.x + v1.y*v1.y + v1.z*v1.z + v1.w*v1.w, r1, a1);
        a2 = fmaf(v2.x*v2.x + v2.y*v2.y + v2.z*v2.z + v2.w*v2.w, r2, a2);
        a3 = fmaf(v3.x*v3.x + v3.y*v3.y + v3.z*v3.z + v3.w*v3.w, r3, a3);
    }
    for (; j < total4; j += stride) {
        float4 v = Z4[j];
        float  r = __ldg(&R[j >> 5]);
        a0 = fmaf(v.x*v.x + v.y*v.y + v.z*v.z + v.w*v.w, r, a0);
    }

    float acc = (a0 + a1) + (a2 + a3);

    // warp reduce
    #pragma unroll
    for (int o = 16; o > 0; o >>= 1)
        acc += __shfl_xor_sync(0xffffffffu, acc, o);

    __shared__ float smem[NTHREADS / 32];
    if ((threadIdx.x & 31) == 0) smem[threadIdx.x >> 5] = acc;
    __syncthreads();

    if (threadIdx.x < 32) {
        float v = (threadIdx.x < NTHREADS / 32) ? smem[threadIdx.x] : 0.f;
        #pragma unroll
        for (int o = (NTHREADS / 32) / 2; o > 0; o >>= 1)
            v += __shfl_xor_sync(0xffffffffu, v, o);
        if (threadIdx.x == 0) g_partials[blockIdx.x] = v;
    }

    // ---- last block finalizes (deterministic: fixed-order sum of partials) ----
    __shared__ bool is_last;
    __threadfence();                                  // partials visible grid-wide
    if (threadIdx.x == 0) {
        unsigned int prev = atomicInc(&g_arrive, NBLOCKS - 1); // wraps -> auto-reset
        is_last = (prev == NBLOCKS - 1);
    }
    __syncthreads();
    if (!is_last) return;

    double dacc = 0.0;
    for (int i = threadIdx.x; i < NBLOCKS; i += NTHREADS)
        dacc += (double)g_partials[i];

    #pragma unroll
    for (int o = 16; o > 0; o >>= 1)
        dacc += __shfl_xor_sync(0xffffffffu, dacc, o);

    __shared__ double dsmem[NTHREADS / 32];
    if ((threadIdx.x & 31) == 0) dsmem[threadIdx.x >> 5] = dacc;
    __syncthreads();

    if (threadIdx.x == 0) {
        double s = 0.0;
        #pragma unroll
        for (int w = 0; w < NTHREADS / 32; w++) s += dsmem[w];
        double lam = exp(s);
        out[0] = (float)(1.0 - exp(-lam));
    }
}

extern "C" void kernel_launch(void* const* d_in, const int* in_sizes, int n_in,
                              void* d_out, int out_size)
{
    const float* a0 = (const float*)d_in[0];
    const float* a1 = (const float*)d_in[1];
    const float* Z; const float* R; int nrows;
    if (in_sizes[0] >= in_sizes[1]) { Z = a0; R = a1; nrows = in_sizes[1]; }
    else                            { Z = a1; R = a0; nrows = in_sizes[0]; }

    bp_fused_kernel<<<NBLOCKS, NTHREADS>>>(Z, R, nrows, (float*)d_out);
}